// round 2
// baseline (speedup 1.0000x reference)
#include <cuda_runtime.h>

// NeuralODE: RNN encoder (reverse scan) -> z0 -> RK4 ODE scan -> decoder.
// B=4096, T=512, OBS=2, LAT=4, NH=20, RNNH=25.
//
// Output layout (flat float):
//   pred_x  [B,T,OBS]   at 0
//   z0      [B,LAT]     at B*T*OBS
//   qz0_mean[B,LAT]     next
//   qz0_logvar[B,LAT]   next
//
// R2 design: ILP=2 (two batches per thread, interleaved chains) to hide
// shfl/elu/butterfly latency inside a single warp. 8 lanes per batch.
// Decoder split into its own massively-parallel kernel reading a z-trajectory
// scratch buffer.

#define BD   4096
#define TD   512
#define OBSD 2
#define LATD 4
#define NHD  20
#define RNNHD 25

#define OFF_Z0   (BD * TD * OBSD)
#define OFF_MEAN (OFF_Z0 + BD * LATD)
#define OFF_LV   (OFF_MEAN + BD * LATD)

__device__ float g_z0[BD * LATD];
__device__ float g_zs[BD * TD * LATD];   // z trajectory for decoder (33.5 MB)

__device__ __forceinline__ float fast_tanh(float x) {
    float e = __expf(2.0f * x);
    return 1.0f - __fdividef(2.0f, e + 1.0f);
}

__device__ __forceinline__ float elu1(float x) {
    float e = __expf(x) - 1.0f;
    return x > 0.0f ? x : e;
}

// ---------------------------------------------------------------------------
// RNN kernel: 8 lanes per batch, 2 batches per thread (ILP=2).
// Each lane owns 4 of 32 zero-padded hidden outputs; weights in registers,
// shared across both batches. 16384 threads = 512 one-warp CTAs.
// ---------------------------------------------------------------------------
__global__ __launch_bounds__(32) void rnn_kernel(
    const float* __restrict__ trajs,   // [B,T,OBS]
    const float* __restrict__ eps,     // [B,LAT]
    const float* __restrict__ i2h_w,   // [27,25]
    const float* __restrict__ i2h_b,   // [25]
    const float* __restrict__ h2o_w,   // [25,8]
    const float* __restrict__ h2o_b,   // [8]
    float* __restrict__ out)
{
    int tid  = threadIdx.x;
    int gt   = blockIdx.x * 32 + tid;
    int grp  = gt >> 3;          // 0..2047
    int sub  = gt & 7;
    int base = tid & ~7;
    int j0   = sub * 4;
    int bA   = grp * 2;
    int bB   = grp * 2 + 1;

    // weight slice in registers (padded 25->32 with zeros)
    float4 w[27];
#pragma unroll
    for (int k = 0; k < 27; k++) {
        float v0 = (j0 + 0 < 25) ? i2h_w[k * 25 + j0 + 0] : 0.0f;
        float v1 = (j0 + 1 < 25) ? i2h_w[k * 25 + j0 + 1] : 0.0f;
        float v2 = (j0 + 2 < 25) ? i2h_w[k * 25 + j0 + 2] : 0.0f;
        float v3 = (j0 + 3 < 25) ? i2h_w[k * 25 + j0 + 3] : 0.0f;
        w[k] = make_float4(v0, v1, v2, v3);
    }
    float4 bias;
    bias.x = (j0 + 0 < 25) ? i2h_b[j0 + 0] : 0.0f;
    bias.y = (j0 + 1 < 25) ? i2h_b[j0 + 1] : 0.0f;
    bias.z = (j0 + 2 < 25) ? i2h_b[j0 + 2] : 0.0f;
    bias.w = (j0 + 3 < 25) ? i2h_b[j0 + 3] : 0.0f;

    float hA[4] = {0.f, 0.f, 0.f, 0.f};
    float hB[4] = {0.f, 0.f, 0.f, 0.f};

    const float2* xpA = reinterpret_cast<const float2*>(trajs) + (size_t)bA * TD;
    const float2* xpB = reinterpret_cast<const float2*>(trajs) + (size_t)bB * TD;
    float2 xA = xpA[TD - 1];
    float2 xB = xpB[TD - 1];

    for (int t = TD - 1; t >= 0; --t) {
        float2 xAn = (t > 0) ? xpA[t - 1] : make_float2(0.f, 0.f);
        float2 xBn = (t > 0) ? xpB[t - 1] : make_float2(0.f, 0.f);

        float aA[4], aB[4];
        aA[0] = bias.x; aA[1] = bias.y; aA[2] = bias.z; aA[3] = bias.w;
        aB[0] = bias.x; aB[1] = bias.y; aB[2] = bias.z; aB[3] = bias.w;

        aA[0] = fmaf(xA.x, w[0].x, aA[0]); aB[0] = fmaf(xB.x, w[0].x, aB[0]);
        aA[1] = fmaf(xA.x, w[0].y, aA[1]); aB[1] = fmaf(xB.x, w[0].y, aB[1]);
        aA[2] = fmaf(xA.x, w[0].z, aA[2]); aB[2] = fmaf(xB.x, w[0].z, aB[2]);
        aA[3] = fmaf(xA.x, w[0].w, aA[3]); aB[3] = fmaf(xB.x, w[0].w, aB[3]);
        aA[0] = fmaf(xA.y, w[1].x, aA[0]); aB[0] = fmaf(xB.y, w[1].x, aB[0]);
        aA[1] = fmaf(xA.y, w[1].y, aA[1]); aB[1] = fmaf(xB.y, w[1].y, aB[1]);
        aA[2] = fmaf(xA.y, w[1].z, aA[2]); aB[2] = fmaf(xB.y, w[1].z, aB[2]);
        aA[3] = fmaf(xA.y, w[1].w, aA[3]); aB[3] = fmaf(xB.y, w[1].w, aB[3]);

#pragma unroll
        for (int k = 0; k < RNNHD; k++) {
            float hvA = __shfl_sync(0xffffffffu, hA[k & 3], base + (k >> 2));
            float hvB = __shfl_sync(0xffffffffu, hB[k & 3], base + (k >> 2));
            const float4 wk = w[k + 2];
            aA[0] = fmaf(hvA, wk.x, aA[0]); aB[0] = fmaf(hvB, wk.x, aB[0]);
            aA[1] = fmaf(hvA, wk.y, aA[1]); aB[1] = fmaf(hvB, wk.y, aB[1]);
            aA[2] = fmaf(hvA, wk.z, aA[2]); aB[2] = fmaf(hvB, wk.z, aB[2]);
            aA[3] = fmaf(hvA, wk.w, aA[3]); aB[3] = fmaf(hvB, wk.w, aB[3]);
        }
#pragma unroll
        for (int i = 0; i < 4; i++) { hA[i] = fast_tanh(aA[i]); hB[i] = fast_tanh(aB[i]); }
        xA = xAn; xB = xBn;
    }

    // h2o: lane computes out[sub] for both batches
    float wo[RNNHD];
#pragma unroll
    for (int k = 0; k < RNNHD; k++) wo[k] = h2o_w[k * 8 + sub];
    float oA = h2o_b[sub], oB = h2o_b[sub];
#pragma unroll
    for (int k = 0; k < RNNHD; k++) {
        float hvA = __shfl_sync(0xffffffffu, hA[k & 3], base + (k >> 2));
        float hvB = __shfl_sync(0xffffffffu, hB[k & 3], base + (k >> 2));
        oA = fmaf(hvA, wo[k], oA);
        oB = fmaf(hvB, wo[k], oB);
    }
    float lvA = __shfl_sync(0xffffffffu, oA, base + sub + 4);
    float lvB = __shfl_sync(0xffffffffu, oB, base + sub + 4);

    if (sub < 4) {
        float z0A = eps[bA * LATD + sub] * __expf(0.5f * lvA) + oA;
        float z0B = eps[bB * LATD + sub] * __expf(0.5f * lvB) + oB;
        out[OFF_MEAN + bA * LATD + sub] = oA;
        out[OFF_MEAN + bB * LATD + sub] = oB;
        out[OFF_Z0 + bA * LATD + sub] = z0A;
        out[OFF_Z0 + bB * LATD + sub] = z0B;
        g_z0[bA * LATD + sub] = z0A;
        g_z0[bB * LATD + sub] = z0B;
    } else {
        out[OFF_LV + bA * LATD + (sub - 4)] = oA;
        out[OFF_LV + bB * LATD + (sub - 4)] = oB;
    }
}

// ---------------------------------------------------------------------------
// ODE kernel: 8 lanes per batch (each owns 3 of 24 padded hidden units),
// 2 batches per thread (ILP=2). All weights in registers. Writes the full z
// trajectory to g_zs; decoder runs separately.
// 16384 threads = 512 one-warp CTAs.
// ---------------------------------------------------------------------------
__global__ __launch_bounds__(32) void ode_kernel(
    const float* __restrict__ ts,
    const float* __restrict__ f1_w, const float* __restrict__ f1_b,
    const float* __restrict__ f2_w, const float* __restrict__ f2_b,
    const float* __restrict__ f3_w, const float* __restrict__ f3_b)
{
    __shared__ float sts[TD];
    int tid = threadIdx.x;
    for (int i = tid; i < TD; i += 32) sts[i] = ts[i];
    __syncwarp();

    int gt   = blockIdx.x * 32 + tid;
    int grp  = gt >> 3;          // 0..2047
    int sub  = gt & 7;
    int base = tid & ~7;
    int j0   = sub * 3;          // owned hidden units j0..j0+2 (pad >= 20)
    int bA   = grp * 2;
    int bB   = grp * 2 + 1;

    // register weights (zero-padded beyond 20)
    float w1[4][3], b1[3], w2[NHD][3], b2[3], w3[3][4], b3[4];
#pragma unroll
    for (int i = 0; i < 3; i++) {
        bool v = (j0 + i) < NHD;
        b1[i] = v ? f1_b[j0 + i] : 0.0f;
        b2[i] = v ? f2_b[j0 + i] : 0.0f;
#pragma unroll
        for (int k = 0; k < 4; k++)
            w1[k][i] = v ? f1_w[k * NHD + j0 + i] : 0.0f;
#pragma unroll
        for (int k = 0; k < NHD; k++)
            w2[k][i] = v ? f2_w[k * NHD + j0 + i] : 0.0f;
#pragma unroll
        for (int o = 0; o < 4; o++)
            w3[i][o] = v ? f3_w[(j0 + i) * 4 + o] : 0.0f;
    }
#pragma unroll
    for (int o = 0; o < 4; o++) b3[o] = f3_b[o];

    float zA[4], zB[4];
    {
        float4 a = *reinterpret_cast<const float4*>(&g_z0[bA * LATD]);
        float4 b = *reinterpret_cast<const float4*>(&g_z0[bB * LATD]);
        zA[0] = a.x; zA[1] = a.y; zA[2] = a.z; zA[3] = a.w;
        zB[0] = b.x; zB[1] = b.y; zB[2] = b.z; zB[3] = b.w;
    }

    // dual-batch f eval: inA/inB -> koA/koB (replicated in all 8 lanes)
    auto feval2 = [&](const float* inA, const float* inB, float* koA, float* koB) {
        float u1oA[3], u1oB[3];
#pragma unroll
        for (int i = 0; i < 3; i++) {
            float aA = b1[i], aB = b1[i];
#pragma unroll
            for (int k = 0; k < 4; k++) {
                aA = fmaf(inA[k], w1[k][i], aA);
                aB = fmaf(inB[k], w1[k][i], aB);
            }
            u1oA[i] = elu1(aA);
            u1oB[i] = elu1(aB);
        }
        float u1A[NHD], u1B[NHD];
#pragma unroll
        for (int k = 0; k < NHD; k++) {
            u1A[k] = __shfl_sync(0xffffffffu, u1oA[k % 3], base + k / 3);
            u1B[k] = __shfl_sync(0xffffffffu, u1oB[k % 3], base + k / 3);
        }
        float u2A[3], u2B[3];
#pragma unroll
        for (int i = 0; i < 3; i++) {
            float aA = b2[i], aB = b2[i];
#pragma unroll
            for (int k = 0; k < NHD; k++) {
                aA = fmaf(u1A[k], w2[k][i], aA);
                aB = fmaf(u1B[k], w2[k][i], aB);
            }
            u2A[i] = elu1(aA);
            u2B[i] = elu1(aB);
        }
#pragma unroll
        for (int o = 0; o < 4; o++) {
            float pA = 0.0f, pB = 0.0f;
#pragma unroll
            for (int i = 0; i < 3; i++) {
                pA = fmaf(u2A[i], w3[i][o], pA);
                pB = fmaf(u2B[i], w3[i][o], pB);
            }
            pA += __shfl_xor_sync(0xffffffffu, pA, 1);
            pB += __shfl_xor_sync(0xffffffffu, pB, 1);
            pA += __shfl_xor_sync(0xffffffffu, pA, 2);
            pB += __shfl_xor_sync(0xffffffffu, pB, 2);
            pA += __shfl_xor_sync(0xffffffffu, pA, 4);
            pB += __shfl_xor_sync(0xffffffffu, pB, 4);
            koA[o] = pA + b3[o];
            koB[o] = pB + b3[o];
        }
    };

    auto store_z = [&](int t) {
        if (sub == 0) {
            float4 v = make_float4(zA[0], zA[1], zA[2], zA[3]);
            *reinterpret_cast<float4*>(&g_zs[((size_t)bA * TD + t) * LATD]) = v;
        } else if (sub == 1) {
            float4 v = make_float4(zB[0], zB[1], zB[2], zB[3]);
            *reinterpret_cast<float4*>(&g_zs[((size_t)bB * TD + t) * LATD]) = v;
        }
    };

    store_z(0);

    for (int step = 0; step < TD - 1; ++step) {
        float dt  = sts[step + 1] - sts[step];
        float hdt = 0.5f * dt;
        float kA[4], kB[4], accA[4], accB[4], tA[4], tB[4];

        feval2(zA, zB, kA, kB);                    // k1
#pragma unroll
        for (int c = 0; c < 4; c++) {
            accA[c] = kA[c];                 accB[c] = kB[c];
            tA[c] = fmaf(hdt, kA[c], zA[c]); tB[c] = fmaf(hdt, kB[c], zB[c]);
        }
        feval2(tA, tB, kA, kB);                    // k2
#pragma unroll
        for (int c = 0; c < 4; c++) {
            accA[c] = fmaf(2.0f, kA[c], accA[c]); accB[c] = fmaf(2.0f, kB[c], accB[c]);
            tA[c] = fmaf(hdt, kA[c], zA[c]);      tB[c] = fmaf(hdt, kB[c], zB[c]);
        }
        feval2(tA, tB, kA, kB);                    // k3
#pragma unroll
        for (int c = 0; c < 4; c++) {
            accA[c] = fmaf(2.0f, kA[c], accA[c]); accB[c] = fmaf(2.0f, kB[c], accB[c]);
            tA[c] = fmaf(dt, kA[c], zA[c]);       tB[c] = fmaf(dt, kB[c], zB[c]);
        }
        feval2(tA, tB, kA, kB);                    // k4
        float s = dt * (1.0f / 6.0f);
#pragma unroll
        for (int c = 0; c < 4; c++) {
            accA[c] += kA[c];                 accB[c] += kB[c];
            zA[c] = fmaf(s, accA[c], zA[c]);  zB[c] = fmaf(s, accB[c], zB[c]);
        }
        store_z(step + 1);
    }
}

// ---------------------------------------------------------------------------
// Decoder kernel: pred_x[b,t] = relu(z @ d1_w + d1_b) @ d2_w + d2_b.
// 2M independent items; weights hoisted to registers; 8 items per thread.
// ---------------------------------------------------------------------------
#define DEC_THREADS (BD * TD / 8)

__global__ __launch_bounds__(128) void decode_kernel(
    const float* __restrict__ d1_w, const float* __restrict__ d1_b,
    const float* __restrict__ d2_w, const float* __restrict__ d2_b,
    float* __restrict__ out)
{
    float w1[4][NHD], b1[NHD], w2[NHD][2], b2[2];
#pragma unroll
    for (int j = 0; j < NHD; j++) {
        b1[j] = d1_b[j];
#pragma unroll
        for (int k = 0; k < 4; k++) w1[k][j] = d1_w[k * NHD + j];
        w2[j][0] = d2_w[j * 2 + 0];
        w2[j][1] = d2_w[j * 2 + 1];
    }
    b2[0] = d2_b[0]; b2[1] = d2_b[1];

    int tidg = blockIdx.x * 128 + threadIdx.x;
#pragma unroll
    for (int it = 0; it < 8; it++) {
        size_t idx = (size_t)it * DEC_THREADS + tidg;   // = b*T + t, coalesced
        float4 zv = *reinterpret_cast<const float4*>(&g_zs[idx * LATD]);
        float z[4] = {zv.x, zv.y, zv.z, zv.w};
        float p0 = b2[0], p1 = b2[1];
#pragma unroll
        for (int j = 0; j < NHD; j++) {
            float a = b1[j];
#pragma unroll
            for (int k = 0; k < 4; k++) a = fmaf(z[k], w1[k][j], a);
            a = fmaxf(a, 0.0f);
            p0 = fmaf(a, w2[j][0], p0);
            p1 = fmaf(a, w2[j][1], p1);
        }
        *reinterpret_cast<float2*>(&out[idx * OBSD]) = make_float2(p0, p1);
    }
}

extern "C" void kernel_launch(void* const* d_in, const int* in_sizes, int n_in,
                              void* d_out, int out_size)
{
    (void)in_sizes; (void)n_in; (void)out_size;
    const float* trajs = (const float*)d_in[0];
    const float* ts    = (const float*)d_in[1];
    const float* eps   = (const float*)d_in[2];
    const float* i2h_w = (const float*)d_in[3];
    const float* i2h_b = (const float*)d_in[4];
    const float* h2o_w = (const float*)d_in[5];
    const float* h2o_b = (const float*)d_in[6];
    const float* f1_w  = (const float*)d_in[7];
    const float* f1_b  = (const float*)d_in[8];
    const float* f2_w  = (const float*)d_in[9];
    const float* f2_b  = (const float*)d_in[10];
    const float* f3_w  = (const float*)d_in[11];
    const float* f3_b  = (const float*)d_in[12];
    const float* d1_w  = (const float*)d_in[13];
    const float* d1_b  = (const float*)d_in[14];
    const float* d2_w  = (const float*)d_in[15];
    const float* d2_b  = (const float*)d_in[16];
    float* out = (float*)d_out;

    rnn_kernel<<<512, 32>>>(trajs, eps, i2h_w, i2h_b, h2o_w, h2o_b, out);
    ode_kernel<<<512, 32>>>(ts, f1_w, f1_b, f2_w, f2_b, f3_w, f3_b);
    decode_kernel<<<(BD * TD / 8) / 128, 128>>>(d1_w, d1_b, d2_w, d2_b, out);
}